// round 1
// baseline (speedup 1.0000x reference)
#include <cuda_runtime.h>
#include <math.h>

#define B 128
#define T 32
#define S 512
#define H 1024
#define IN_DIM 1024
#define G4 4096          // 4*H
#define KREC 2048        // H (ha) + H (h)

#define SK_GATES 8
#define SK_HTIL 16
#define SK_WOUT 16
#define NSPLIT 4

// ---- output offsets (flattened tuple, fp32) ----
#define OFF_OUT   0ull
#define OFF_H     4194304ull
#define OFF_C     4325376ull
#define OFF_HA    4456448ull
#define OFF_ATTN  4587520ull
#define OFF_PATTN 6684672ull
#define OFF_P     6750208ull
#define OFF_DEHY  6754304ull
#define OFF_LOSS  6885376ull

// ---- scratch (device globals; no runtime allocation) ----
__device__ float g_Xg[(size_t)B * T * G4];        // input @ W_ih[:, :IN].T + b_ih + b_hh
__device__ float g_Wr[(size_t)G4 * KREC];         // [W_ih[:, IN:], W_hh] concat along K
__device__ float g_WattnT[H * H];                 // W_attn transposed
__device__ float g_biasg[G4];
__device__ float g_gates_part[SK_GATES * B * G4];
__device__ float g_htil_part[SK_HTIL * B * H];
__device__ float g_wout_part[SK_WOUT * B * H];
__device__ float g_Arec[B * KREC];                // [ha, h] per batch
__device__ float g_Aout[B * KREC];                // [c_enc, h] per batch
__device__ float g_h[B * H];
__device__ float g_c[B * H];
__device__ float g_logits[B * S];
__device__ float g_part_acc[B * NSPLIT * H];
__device__ float g_part_m[B * NSPLIT];
__device__ float g_part_l[B * NSPLIT];

// ============================================================
// Generic C = A @ W.T  (A:[M,K] row-major, W:[N,K] row-major),
// split-K into gridDim.z partials. BM=BN=128, BK=8, TM=TN=8.
// ============================================================
__global__ __launch_bounds__(256)
void sgemm_tn(const float* __restrict__ A, int lda,
              const float* __restrict__ W, int ldw,
              float* __restrict__ Cpart, int M, int N, int Kslice,
              const float* __restrict__ bias)
{
    const int bn = blockIdx.x, bm = blockIdx.y, bz = blockIdx.z;
    A += (size_t)bm * 128 * lda + (size_t)bz * Kslice;
    W += (size_t)bn * 128 * ldw + (size_t)bz * Kslice;
    float* C = Cpart + (size_t)bz * M * N + (size_t)bm * 128 * N + (size_t)bn * 128;

    __shared__ float As[8][128];
    __shared__ float Bs[8][128];
    const int tid = threadIdx.x;
    const int lr = tid >> 1;
    const int lk = (tid & 1) * 4;
    const int tx = tid & 15, ty = tid >> 4;

    float acc[8][8];
#pragma unroll
    for (int i = 0; i < 8; i++)
#pragma unroll
        for (int j = 0; j < 8; j++) acc[i][j] = 0.f;

    for (int k0 = 0; k0 < Kslice; k0 += 8) {
        float4 a4 = *(const float4*)(A + (size_t)lr * lda + k0 + lk);
        float4 b4 = *(const float4*)(W + (size_t)lr * ldw + k0 + lk);
        __syncthreads();
        As[lk + 0][lr] = a4.x; As[lk + 1][lr] = a4.y;
        As[lk + 2][lr] = a4.z; As[lk + 3][lr] = a4.w;
        Bs[lk + 0][lr] = b4.x; Bs[lk + 1][lr] = b4.y;
        Bs[lk + 2][lr] = b4.z; Bs[lk + 3][lr] = b4.w;
        __syncthreads();
#pragma unroll
        for (int k = 0; k < 8; k++) {
            float ar[8], br[8];
            *(float4*)(ar)     = *(const float4*)&As[k][ty * 8];
            *(float4*)(ar + 4) = *(const float4*)&As[k][ty * 8 + 4];
            *(float4*)(br)     = *(const float4*)&Bs[k][tx * 8];
            *(float4*)(br + 4) = *(const float4*)&Bs[k][tx * 8 + 4];
#pragma unroll
            for (int i = 0; i < 8; i++)
#pragma unroll
                for (int j = 0; j < 8; j++) acc[i][j] += ar[i] * br[j];
        }
    }
#pragma unroll
    for (int i = 0; i < 8; i++) {
        float* crow = C + (size_t)(ty * 8 + i) * N + tx * 8;
#pragma unroll
        for (int j = 0; j < 8; j++) {
            float v = acc[i][j];
            if (bias != nullptr) v += bias[bn * 128 + tx * 8 + j];
            crow[j] = v;
        }
    }
}

// ============================================================
// Setup kernels
// ============================================================
__global__ void prep_kernel(const float* __restrict__ W_ih, const float* __restrict__ W_hh,
                            const float* __restrict__ b_ih, const float* __restrict__ b_hh,
                            const float* __restrict__ W_attn)
{
    size_t stride = (size_t)gridDim.x * blockDim.x;
    size_t start = (size_t)blockIdx.x * blockDim.x + threadIdx.x;
    for (size_t idx = start; idx < (size_t)G4 * KREC; idx += stride) {
        int n = (int)(idx >> 11);
        int k = (int)(idx & 2047);
        g_Wr[idx] = (k < H) ? W_ih[(size_t)n * KREC + IN_DIM + k]
                            : W_hh[(size_t)n * H + (k - H)];
    }
    for (size_t idx = start; idx < (size_t)H * H; idx += stride) {
        int k = (int)(idx >> 10), g = (int)(idx & 1023);
        g_WattnT[idx] = W_attn[(size_t)g * H + k];
    }
    for (size_t idx = start; idx < (size_t)G4; idx += stride)
        g_biasg[idx] = b_ih[idx] + b_hh[idx];
}

__global__ void init_kernel(const float* __restrict__ hh, const float* __restrict__ hc,
                            const float* __restrict__ ha)
{
    int idx = blockIdx.x * blockDim.x + threadIdx.x;
    if (idx < B * H) {
        int b = idx >> 10, n = idx & 1023;
        g_h[idx] = hh[idx];
        g_c[idx] = hc[idx];
        g_Arec[b * KREC + n] = ha[idx];       // ha slot
        g_Arec[b * KREC + H + n] = hh[idx];   // h slot
    }
}

// ============================================================
// LSTM cell: sum gate partials + precomputed Xg, update h/c
// ============================================================
__global__ void lstm_step(int t)
{
    int idx = blockIdx.x * blockDim.x + threadIdx.x;   // B*H threads
    int b = idx >> 10, n = idx & 1023;
    size_t row = ((size_t)b * T + t) * G4;
    float gi = g_Xg[row + n];
    float gf = g_Xg[row + H + n];
    float gg = g_Xg[row + 2 * H + n];
    float go = g_Xg[row + 3 * H + n];
#pragma unroll
    for (int p = 0; p < SK_GATES; p++) {
        const float* gp = g_gates_part + (size_t)p * B * G4 + (size_t)b * G4;
        gi += gp[n]; gf += gp[H + n]; gg += gp[2 * H + n]; go += gp[3 * H + n];
    }
    float i_ = 1.f / (1.f + expf(-gi));
    float f_ = 1.f / (1.f + expf(-gf));
    float g_ = tanhf(gg);
    float o_ = 1.f / (1.f + expf(-go));
    float c_new = f_ * g_c[idx] + i_ * g_;
    float h_new = o_ * tanhf(c_new);
    g_c[idx] = c_new;
    g_h[idx] = h_new;
    g_Arec[b * KREC + H + n] = h_new;
    g_Aout[b * KREC + H + n] = h_new;
}

// ============================================================
// One-pass flash attention over a split of S.
// grid (B, NSPLIT), 256 threads (8 warps), 16 s-rows per warp.
// ============================================================
__global__ __launch_bounds__(256)
void flash_step(const float* __restrict__ enc)
{
    int b = blockIdx.x, sp = blockIdx.y;
    __shared__ float htil[H];
    __shared__ float accS[8][1024];
    __shared__ float wm[8], wl[8], wf[8];
    int tid = threadIdx.x;

    // reduce split-K partials of h~ = h @ W_attn
    for (int j = tid; j < H; j += 256) {
        float s = 0.f;
#pragma unroll
        for (int p = 0; p < SK_HTIL; p++) s += g_htil_part[(size_t)p * B * H + b * H + j];
        htil[j] = s;
    }
    __syncthreads();

    int warp = tid >> 5, lane = tid & 31;
    float m = -1e30f, l = 0.f;
    float acc[32];
#pragma unroll
    for (int i = 0; i < 32; i++) acc[i] = 0.f;

    const float* encb = enc + (size_t)b * S * H;
    int s0 = sp * 128 + warp * 16;
    for (int si = 0; si < 16; si++) {
        int s = s0 + si;
        const float* er = encb + (size_t)s * H + lane;
        float v[32];
#pragma unroll
        for (int i = 0; i < 32; i++) v[i] = er[i * 32];
        float d = 0.f;
#pragma unroll
        for (int i = 0; i < 32; i++) d += v[i] * htil[lane + i * 32];
#pragma unroll
        for (int off = 16; off > 0; off >>= 1) d += __shfl_xor_sync(0xffffffffu, d, off);
        if (lane == 0) g_logits[b * S + s] = d;
        float mn = fmaxf(m, d);
        float sc = __expf(m - mn);
        float w  = __expf(d - mn);
        l = l * sc + w;
#pragma unroll
        for (int i = 0; i < 32; i++) acc[i] = acc[i] * sc + w * v[i];
        m = mn;
    }
#pragma unroll
    for (int i = 0; i < 32; i++) accS[warp][lane + i * 32] = acc[i];
    if (lane == 0) { wm[warp] = m; wl[warp] = l; }
    __syncthreads();
    if (tid == 0) {
        float M = -1e30f;
        for (int w0 = 0; w0 < 8; w0++) M = fmaxf(M, wm[w0]);
        float L = 0.f;
        for (int w0 = 0; w0 < 8; w0++) { float f = __expf(wm[w0] - M); wf[w0] = f; L += wl[w0] * f; }
        g_part_m[b * NSPLIT + sp] = M;
        g_part_l[b * NSPLIT + sp] = L;
    }
    __syncthreads();
    for (int j = tid; j < H; j += 256) {
        float s = 0.f;
#pragma unroll
        for (int w0 = 0; w0 < 8; w0++) s += accS[w0][j] * wf[w0];
        g_part_acc[((size_t)b * NSPLIT + sp) * H + j] = s;
    }
}

// combine split partials -> c_enc; write softmax probs for step t
__global__ void combine_step(int t, float* __restrict__ out)
{
    int b = blockIdx.x, tid = threadIdx.x;
    __shared__ float fP[NSPLIT];
    __shared__ float sM, sL;
    if (tid == 0) {
        float M = -1e30f;
        for (int p = 0; p < NSPLIT; p++) M = fmaxf(M, g_part_m[b * NSPLIT + p]);
        float L = 0.f;
        for (int p = 0; p < NSPLIT; p++) {
            float f = __expf(g_part_m[b * NSPLIT + p] - M);
            fP[p] = f;
            L += g_part_l[b * NSPLIT + p] * f;
        }
        sM = M; sL = L;
    }
    __syncthreads();
    float invL = 1.f / sL;
    for (int j = tid; j < H; j += 256) {
        float ce = 0.f;
        for (int p = 0; p < NSPLIT; p++) ce += g_part_acc[((size_t)b * NSPLIT + p) * H + j] * fP[p];
        g_Aout[b * KREC + j] = ce * invL;
    }
    float M = sM;
    for (int s = tid; s < S; s += 256)
        out[OFF_ATTN + (size_t)t * B * S + (size_t)b * S + s] =
            __expf(g_logits[b * S + s] - M) * invL;
}

// ha = [c_enc, h] @ W_out.T + b_out  (sum split-K partials); write output_
__global__ void haepi_step(int t, float* __restrict__ out, const float* __restrict__ b_out)
{
    int idx = blockIdx.x * blockDim.x + threadIdx.x;   // B*H
    int b = idx >> 10, n = idx & 1023;
    float v = b_out[n];
#pragma unroll
    for (int p = 0; p < SK_WOUT; p++) v += g_wout_part[(size_t)p * B * H + idx];
    g_Arec[b * KREC + n] = v;
    out[OFF_OUT + ((size_t)b * T + t) * H + n] = v;
}

// p = sigmoid([x_k, h, c_enc] @ W_pt.T + b_pt)
__global__ void pgen_step(int t, const float* __restrict__ input_,
                          const float* __restrict__ W_pt, const float* __restrict__ b_pt,
                          float* __restrict__ out)
{
    int b = blockIdx.x, tid = threadIdx.x;
    const float* xk = input_ + ((size_t)b * T + t) * IN_DIM;
    float s = 0.f;
    for (int k = tid; k < IN_DIM; k += 256) s += W_pt[k] * xk[k];
    for (int k = tid; k < H; k += 256)      s += W_pt[IN_DIM + k] * g_h[b * H + k];
    for (int k = tid; k < H; k += 256)      s += W_pt[IN_DIM + H + k] * g_Aout[b * KREC + k];
    __shared__ float red[256];
    red[tid] = s;
    __syncthreads();
    for (int st = 128; st > 0; st >>= 1) {
        if (tid < st) red[tid] += red[tid + st];
        __syncthreads();
    }
    if (tid == 0) {
        float p = 1.f / (1.f + expf(-(red[0] + b_pt[0])));
        out[OFF_P + (size_t)b * T + t] = p;
    }
}

__global__ void final_kernel(const float* __restrict__ past_attn_in,
                             const float* __restrict__ past_dehy_in,
                             float* __restrict__ out)
{
    int idx = blockIdx.x * blockDim.x + threadIdx.x;
    if (idx < B * H) {
        out[OFF_H + idx] = g_h[idx];
        out[OFF_C + idx] = g_c[idx];
        int b = idx >> 10, n = idx & 1023;
        out[OFF_HA + idx] = g_Arec[b * KREC + n];
        out[OFF_DEHY + idx] = past_dehy_in[idx];
    }
    if (idx < B * S) out[OFF_PATTN + idx] = past_attn_in[idx];
    if (idx == 0) out[OFF_LOSS] = 0.f;
}

// ============================================================
extern "C" void kernel_launch(void* const* d_in, const int* in_sizes, int n_in,
                              void* d_out, int out_size)
{
    // skip leading scalar 'idx' input if present
    int base = (in_sizes[0] == 1) ? 1 : 0;
    const float* input_    = (const float*)d_in[base + 0];
    const float* hidden_h  = (const float*)d_in[base + 1];
    const float* hidden_c  = (const float*)d_in[base + 2];
    const float* h_attn    = (const float*)d_in[base + 3];
    const float* enc       = (const float*)d_in[base + 4];
    const float* past_attn = (const float*)d_in[base + 5];
    // d_in[base+6] = p_gen (unused input)
    const float* past_dehy = (const float*)d_in[base + 7];
    const float* W_ih  = (const float*)d_in[base + 8];
    const float* b_ih  = (const float*)d_in[base + 9];
    const float* W_hh  = (const float*)d_in[base + 10];
    const float* b_hh  = (const float*)d_in[base + 11];
    const float* W_attn= (const float*)d_in[base + 12];
    const float* W_out = (const float*)d_in[base + 13];
    const float* b_out = (const float*)d_in[base + 14];
    const float* W_pt  = (const float*)d_in[base + 15];
    const float* b_pt  = (const float*)d_in[base + 16];
    float* out = (float*)d_out;

    float *pXg, *pWr, *pWT, *pbg, *pGates, *pHtil, *pWoutp, *pArec, *pAout, *pH;
    cudaGetSymbolAddress((void**)&pXg,   g_Xg);
    cudaGetSymbolAddress((void**)&pWr,   g_Wr);
    cudaGetSymbolAddress((void**)&pWT,   g_WattnT);
    cudaGetSymbolAddress((void**)&pbg,   g_biasg);
    cudaGetSymbolAddress((void**)&pGates,g_gates_part);
    cudaGetSymbolAddress((void**)&pHtil, g_htil_part);
    cudaGetSymbolAddress((void**)&pWoutp,g_wout_part);
    cudaGetSymbolAddress((void**)&pArec, g_Arec);
    cudaGetSymbolAddress((void**)&pAout, g_Aout);
    cudaGetSymbolAddress((void**)&pH,    g_h);

    prep_kernel<<<2048, 256>>>(W_ih, W_hh, b_ih, b_hh, W_attn);
    init_kernel<<<(B * H + 255) / 256, 256>>>(hidden_h, hidden_c, h_attn);

    // Xg = input_ @ W_ih[:, :IN].T + (b_ih + b_hh) ; rows indexed (b*T + t)
    sgemm_tn<<<dim3(G4 / 128, (B * T) / 128, 1), 256>>>(
        input_, IN_DIM, W_ih, KREC, pXg, B * T, G4, IN_DIM, pbg);

    for (int t = 0; t < T; t++) {
        // gates partial: [ha, h] @ [W_ih[:,IN:], W_hh].T
        sgemm_tn<<<dim3(G4 / 128, 1, SK_GATES), 256>>>(
            pArec, KREC, pWr, KREC, pGates, B, G4, KREC / SK_GATES, nullptr);
        lstm_step<<<(B * H) / 256, 256>>>(t);
        // h~ = h @ W_attn  (via W_attn^T rows)
        sgemm_tn<<<dim3(H / 128, 1, SK_HTIL), 256>>>(
            pH, H, pWT, H, pHtil, B, H, H / SK_HTIL, nullptr);
        flash_step<<<dim3(B, NSPLIT), 256>>>(enc);
        combine_step<<<B, 256>>>(t, out);
        // ha partial: [c_enc, h] @ W_out.T
        sgemm_tn<<<dim3(H / 128, 1, SK_WOUT), 256>>>(
            pAout, KREC, W_out, KREC, pWoutp, B, H, KREC / SK_WOUT, nullptr);
        haepi_step<<<(B * H) / 256, 256>>>(t, out, b_out);
        pgen_step<<<B, 256>>>(t, input_, W_pt, b_pt, out);
    }
    final_kernel<<<(B * H + 255) / 256, 256>>>(past_attn, past_dehy, out);
}